// round 1
// baseline (speedup 1.0000x reference)
#include <cuda_runtime.h>
#include <math.h>

#define LDSM 72           // padded row stride (floats): 288B, 16B-aligned, shifts banks per row
#define EPSV 1e-4f
#define NAGG 7            // aggressive sign iterations
#define NPOL 5            // exact Newton-Schulz polish iterations
#define NITER (NAGG + NPOL)

// 64x64x64 fp32 GEMM core: acc(4x4) = As[r0..r0+3][:] * Bs[:][c0..c0+3]
__device__ __forceinline__ void mm64(float acc[4][4],
                                     const float* __restrict__ As,
                                     const float* __restrict__ Bs,
                                     int r0, int c0)
{
#pragma unroll
    for (int i = 0; i < 4; i++)
#pragma unroll
        for (int j = 0; j < 4; j++) acc[i][j] = 0.0f;

#pragma unroll 4
    for (int k0 = 0; k0 < 64; k0 += 4) {
        float4 av[4], bv[4];
#pragma unroll
        for (int i = 0; i < 4; i++)
            av[i] = *reinterpret_cast<const float4*>(As + (r0 + i) * LDSM + k0);
#pragma unroll
        for (int kk = 0; kk < 4; kk++)
            bv[kk] = *reinterpret_cast<const float4*>(Bs + (k0 + kk) * LDSM + c0);
#pragma unroll
        for (int kk = 0; kk < 4; kk++) {
            const float b0 = bv[kk].x, b1 = bv[kk].y, b2 = bv[kk].z, b3 = bv[kk].w;
#pragma unroll
            for (int i = 0; i < 4; i++) {
                const float a = (kk == 0) ? av[i].x : (kk == 1) ? av[i].y
                              : (kk == 2) ? av[i].z : av[i].w;
                acc[i][0] = fmaf(a, b0, acc[i][0]);
                acc[i][1] = fmaf(a, b1, acc[i][1]);
                acc[i][2] = fmaf(a, b2, acc[i][2]);
                acc[i][3] = fmaf(a, b3, acc[i][3]);
            }
        }
    }
}

extern "C" __global__ void __launch_bounds__(256, 3)
reeig_kernel(const float* __restrict__ xg, float* __restrict__ outg, int nmat)
{
    extern __shared__ float sm[];
    float* Abuf = sm;                  // A = X - eps*I
    float* Sbuf = Abuf + 64 * LDSM;    // current sign iterate
    float* Pbuf = Sbuf + 64 * LDSM;    // S^2 scratch / final S*A
    float* Qbuf = Pbuf + 64 * LDSM;    // next sign iterate
    float* red  = Qbuf + 64 * LDSM;    // 16 floats reduction scratch

    const int mat = blockIdx.x;
    if (mat >= nmat) return;
    const float* X = xg + (size_t)mat * 4096;
    float*       O = outg + (size_t)mat * 4096;

    const int t  = threadIdx.x;
    const int r0 = (t >> 4) * 4;       // 16x16 thread grid, 4x4 tiles
    const int c0 = (t & 15) * 4;

    // Load A = X - eps*I
    for (int idx = t; idx < 4096; idx += 256) {
        const int r = idx >> 6, c = idx & 63;
        float v = X[idx];
        if (r == c) v -= EPSV;
        Abuf[r * LDSM + c] = v;
    }
    __syncthreads();

    float acc[4][4];

    // P = A*A  (A^2)
    mm64(acc, Abuf, Abuf, r0, c0);
#pragma unroll
    for (int i = 0; i < 4; i++)
#pragma unroll
        for (int j = 0; j < 4; j++) Pbuf[(r0 + i) * LDSM + c0 + j] = acc[i][j];
    __syncthreads();

    // ||A^4||_F^2 = sum of squares of (P*P) — computed without storing P*P
    mm64(acc, Pbuf, Pbuf, r0, c0);
    float part = 0.0f;
#pragma unroll
    for (int i = 0; i < 4; i++)
#pragma unroll
        for (int j = 0; j < 4; j++) part = fmaf(acc[i][j], acc[i][j], part);

    // block reduction -> inv_s
#pragma unroll
    for (int off = 16; off; off >>= 1)
        part += __shfl_xor_sync(0xffffffffu, part, off);
    if ((t & 31) == 0) red[t >> 5] = part;
    __syncthreads();
    if (t == 0) {
        float tot = 0.0f;
        for (int w = 0; w < 8; w++) tot += red[w];
        // s = 1.02 * (||A^4||_F)^(1/4) = 1.02 * tot^(1/8) >= 1.02 * lambda_max
        const float s = 1.02f * exp2f(0.125f * log2f(fmaxf(tot, 1e-30f)));
        red[8] = 1.0f / s;
    }
    __syncthreads();
    const float inv_s = red[8];

    // S0 = A / s   (spectrum in [-0.98, 0.98])
    for (int idx = t; idx < 4096; idx += 256) {
        const int r = idx >> 6, c = idx & 63;
        Sbuf[r * LDSM + c] = Abuf[r * LDSM + c] * inv_s;
    }
    __syncthreads();

    // Matrix sign iterations: S <- ca*S + cb*S^3
    float* S = Sbuf;
    float* Q = Qbuf;
#pragma unroll 1
    for (int it = 0; it < NITER; it++) {
        const bool agg = (it < NAGG);
        const float ca = agg ? 2.325f      : 1.5f;
        const float cb = agg ? -1.8619375f : -0.5f;

        mm64(acc, S, S, r0, c0);                   // P = S^2
#pragma unroll
        for (int i = 0; i < 4; i++)
#pragma unroll
            for (int j = 0; j < 4; j++) Pbuf[(r0 + i) * LDSM + c0 + j] = acc[i][j];
        __syncthreads();

        mm64(acc, S, Pbuf, r0, c0);                // acc = S^3
#pragma unroll
        for (int i = 0; i < 4; i++)
#pragma unroll
            for (int j = 0; j < 4; j++)
                Q[(r0 + i) * LDSM + c0 + j] =
                    fmaf(cb, acc[i][j], ca * S[(r0 + i) * LDSM + c0 + j]);
        __syncthreads();

        float* tmp = S; S = Q; Q = tmp;
    }

    // P = S * A  ≈ |A|
    mm64(acc, S, Abuf, r0, c0);
#pragma unroll
    for (int i = 0; i < 4; i++)
#pragma unroll
        for (int j = 0; j < 4; j++) Pbuf[(r0 + i) * LDSM + c0 + j] = acc[i][j];
    __syncthreads();

    // Out = (X + eps*I)/2 + sym(|A|)/2 = A/2 + eps*I + (P + P^T)/4
    for (int idx = t; idx < 4096; idx += 256) {
        const int r = idx >> 6, c = idx & 63;
        float v = 0.5f * Abuf[r * LDSM + c]
                + 0.25f * (Pbuf[r * LDSM + c] + Pbuf[c * LDSM + r]);
        if (r == c) v += EPSV;
        O[idx] = v;
    }
}

extern "C" void kernel_launch(void* const* d_in, const int* in_sizes, int n_in,
                              void* d_out, int out_size)
{
    const float* x  = (const float*)d_in[0];
    float* out      = (float*)d_out;
    const int nmat  = in_sizes[0] / 4096;

    const int smem_bytes = (4 * 64 * LDSM + 16) * (int)sizeof(float);  // 73792
    cudaFuncSetAttribute(reeig_kernel, cudaFuncAttributeMaxDynamicSharedMemorySize,
                         smem_bytes);
    reeig_kernel<<<nmat, 256, smem_bytes>>>(x, out, nmat);
}

// round 4
// speedup vs baseline: 1.0780x; 1.0780x over previous
#include <cuda_runtime.h>
#include <math.h>

#define LDSM  72          // row stride (floats); 72 mod 32 = 8 -> conflict-free MMA frags
#define EPSV  1e-4f
#define NAGG  7
#define NITER 12          // 7 aggressive + 5 Newton-Schulz polish

// round-to-nearest fp32 -> tf32 (valid fp32 bit pattern, low 13 mantissa bits zero)
__device__ __forceinline__ unsigned f2tf(float x) {
    unsigned r; asm("cvt.rna.tf32.f32 %0, %1;" : "=r"(r) : "f"(x)); return r;
}

__device__ __forceinline__ void mma8(float* d, const unsigned* a, const unsigned* b) {
    asm volatile("mma.sync.aligned.m16n8k8.row.col.f32.tf32.tf32.f32 "
                 "{%0,%1,%2,%3}, {%4,%5,%6,%7}, {%8,%9}, {%0,%1,%2,%3};"
                 : "+f"(d[0]), "+f"(d[1]), "+f"(d[2]), "+f"(d[3])
                 : "r"(a[0]), "r"(a[1]), "r"(a[2]), "r"(a[3]), "r"(b[0]), "r"(b[1]));
}

// Warp computes a 16x32 tile of D = A * B (B read DIRECTLY as B[k][n]: no symmetry
// assumption anywhere). 4xTF32 split: hi*hi + lo*hi + hi*lo + lo*lo, fp32-class.
__device__ __forceinline__ void warp_gemm(float acc[4][4],
                                          const float* __restrict__ As,
                                          const float* __restrict__ Bs,
                                          int mr, int nc, int g, int t4)
{
#pragma unroll
    for (int nt = 0; nt < 4; nt++)
#pragma unroll
        for (int i = 0; i < 4; i++) acc[nt][i] = 0.0f;

#pragma unroll
    for (int k0 = 0; k0 < 64; k0 += 8) {
        // A fragment: rows mr+g / mr+8+g, cols k0+t4 / k0+t4+4
        unsigned ahi[4], alo[4];
        {
            const float* ap = As + (mr + g) * LDSM + k0 + t4;
            float x0 = ap[0];
            float x1 = ap[8 * LDSM];
            float x2 = ap[4];
            float x3 = ap[8 * LDSM + 4];
            ahi[0] = f2tf(x0); ahi[1] = f2tf(x1); ahi[2] = f2tf(x2); ahi[3] = f2tf(x3);
            alo[0] = f2tf(x0 - __uint_as_float(ahi[0]));
            alo[1] = f2tf(x1 - __uint_as_float(ahi[1]));
            alo[2] = f2tf(x2 - __uint_as_float(ahi[2]));
            alo[3] = f2tf(x3 - __uint_as_float(ahi[3]));
        }
        // B fragments: b0 = B[k0+t4][nc+nt*8+g], b1 = B[k0+t4+4][...]
        unsigned bhi[4][2], blo[4][2];
        const float* bp0 = Bs + (k0 + t4) * LDSM + nc + g;
        const float* bp1 = bp0 + 4 * LDSM;
#pragma unroll
        for (int nt = 0; nt < 4; nt++) {
            float y0 = bp0[nt * 8];
            float y1 = bp1[nt * 8];
            bhi[nt][0] = f2tf(y0); bhi[nt][1] = f2tf(y1);
            blo[nt][0] = f2tf(y0 - __uint_as_float(bhi[nt][0]));
            blo[nt][1] = f2tf(y1 - __uint_as_float(bhi[nt][1]));
        }
#pragma unroll
        for (int nt = 0; nt < 4; nt++) {
            mma8(acc[nt], ahi, bhi[nt]);
            mma8(acc[nt], alo, bhi[nt]);
            mma8(acc[nt], ahi, blo[nt]);
            mma8(acc[nt], alo, blo[nt]);
        }
    }
}

__device__ __forceinline__ void store_acc(float* __restrict__ D, const float acc[4][4],
                                          int mr, int nc, int g, int t4)
{
#pragma unroll
    for (int nt = 0; nt < 4; nt++) {
        int r = mr + g, c = nc + nt * 8 + 2 * t4;
        *(float2*)&D[r * LDSM + c]       = make_float2(acc[nt][0], acc[nt][1]);
        *(float2*)&D[(r + 8) * LDSM + c] = make_float2(acc[nt][2], acc[nt][3]);
    }
}

extern "C" __global__ void __launch_bounds__(256, 3)
reeig_mma4(const float* __restrict__ xg, float* __restrict__ outg, int nmat)
{
    extern __shared__ float sm[];
    float* Abuf = sm;                  // A = X - eps*I (preserved)
    float* Sbuf = Abuf + 64 * LDSM;
    float* Pbuf = Sbuf + 64 * LDSM;
    float* Qbuf = Pbuf + 64 * LDSM;
    float* red  = Qbuf + 64 * LDSM;    // 16 floats

    const int mat = blockIdx.x;
    if (mat >= nmat) return;
    const float* X = xg + (size_t)mat * 4096;
    float*       O = outg + (size_t)mat * 4096;

    const int t = threadIdx.x;
    const int warp = t >> 5, lane = t & 31;
    const int g = lane >> 2, t4 = lane & 3;
    const int mr = (warp & 3) * 16;    // 8 warps: 4 row-bands x 2 col-bands
    const int nc = (warp >> 2) * 32;

    // A = X - eps*I
    for (int idx = t; idx < 4096; idx += 256) {
        int r = idx >> 6, c = idx & 63;
        float v = X[idx];
        if (r == c) v -= EPSV;
        Abuf[r * LDSM + c] = v;
    }
    __syncthreads();

    float acc[4][4];

    // P = A*A   (4-split: fp32-class, matching R1 prep numerics)
    warp_gemm(acc, Abuf, Abuf, mr, nc, g, t4);
    store_acc(Pbuf, acc, mr, nc, g, t4);
    __syncthreads();

    // ||A^4||_F^2 = sum of squares of P*P (no store)
    warp_gemm(acc, Pbuf, Pbuf, mr, nc, g, t4);
    float part = 0.0f;
#pragma unroll
    for (int nt = 0; nt < 4; nt++)
#pragma unroll
        for (int i = 0; i < 4; i++) part = fmaf(acc[nt][i], acc[nt][i], part);
#pragma unroll
    for (int off = 16; off; off >>= 1)
        part += __shfl_xor_sync(0xffffffffu, part, off);
    if (lane == 0) red[warp] = part;
    __syncthreads();
    if (t == 0) {
        float tot = 0.0f;
        for (int w = 0; w < 8; w++) tot += red[w];
        // s = 1.02 * ||A^4||_F^(1/4) = 1.02 * tot^(1/8) >= 1.02 * lambda_max
        float s = 1.02f * exp2f(0.125f * log2f(fmaxf(tot, 1e-30f)));
        red[8] = 1.0f / s;
    }
    __syncthreads();
    const float inv_s = red[8];

    // S = A / s   (spectrum in [-0.98, 0.98])
    for (int idx = t; idx < 4096; idx += 256) {
        int r = idx >> 6, c = idx & 63;
        Sbuf[r * LDSM + c] = Abuf[r * LDSM + c] * inv_s;
    }
    __syncthreads();

    // sign iterations: S <- ca*S + cb*S^3
    float* Sc = Sbuf;
    float* Qc = Qbuf;
#pragma unroll 1
    for (int it = 0; it < NITER; it++) {
        const float ca = (it < NAGG) ? 2.325f      : 1.5f;
        const float cb = (it < NAGG) ? -1.8619375f : -0.5f;

        warp_gemm(acc, Sc, Sc, mr, nc, g, t4);           // P = S^2
        store_acc(Pbuf, acc, mr, nc, g, t4);
        __syncthreads();

        warp_gemm(acc, Sc, Pbuf, mr, nc, g, t4);         // acc = S^3
#pragma unroll
        for (int nt = 0; nt < 4; nt++) {
            int r = mr + g, c = nc + nt * 8 + 2 * t4;
            float2 s1 = *(const float2*)&Sc[r * LDSM + c];
            float2 s2 = *(const float2*)&Sc[(r + 8) * LDSM + c];
            *(float2*)&Qc[r * LDSM + c] =
                make_float2(fmaf(cb, acc[nt][0], ca * s1.x),
                            fmaf(cb, acc[nt][1], ca * s1.y));
            *(float2*)&Qc[(r + 8) * LDSM + c] =
                make_float2(fmaf(cb, acc[nt][2], ca * s2.x),
                            fmaf(cb, acc[nt][3], ca * s2.y));
        }
        __syncthreads();

        float* tmp = Sc; Sc = Qc; Qc = tmp;              // even NITER -> ends in Sbuf
    }

    // M = S * A ~= |A|
    warp_gemm(acc, Sc, Abuf, mr, nc, g, t4);
    store_acc(Pbuf, acc, mr, nc, g, t4);
    __syncthreads();

    // out = A/2 + eps*I + (M + M^T)/4
    for (int idx = t; idx < 4096; idx += 256) {
        int r = idx >> 6, c = idx & 63;
        float v = 0.5f * Abuf[r * LDSM + c]
                + 0.25f * (Pbuf[r * LDSM + c] + Pbuf[c * LDSM + r]);
        if (r == c) v += EPSV;
        O[idx] = v;
    }
}

extern "C" void kernel_launch(void* const* d_in, const int* in_sizes, int n_in,
                              void* d_out, int out_size)
{
    const float* x  = (const float*)d_in[0];
    float* out      = (float*)d_out;
    const int nmat  = in_sizes[0] / 4096;

    const int smem_bytes = (4 * 64 * LDSM + 16) * (int)sizeof(float);  // 73792
    cudaFuncSetAttribute(reeig_mma4, cudaFuncAttributeMaxDynamicSharedMemorySize,
                         smem_bytes);
    reeig_mma4<<<nmat, 256, smem_bytes>>>(x, out, nmat);
}

// round 5
// speedup vs baseline: 1.8513x; 1.7174x over previous
#include <cuda_runtime.h>
#include <math.h>

#define LDSM  72          // row stride (floats): B-frag loads conflict-free; A-frag 2-way (as R4)
#define EPSV  1e-4f
#define NAGG  5
#define NITER 10          // 5 aggressive + 5 Newton-Schulz polish

// round-to-nearest fp32 -> tf32 (valid fp32 bit pattern, low 13 mantissa bits zero)
__device__ __forceinline__ unsigned f2tf(float x) {
    unsigned r; asm("cvt.rna.tf32.f32 %0, %1;" : "=r"(r) : "f"(x)); return r;
}

__device__ __forceinline__ void mma8(float* d, const unsigned* a, const unsigned* b) {
    asm volatile("mma.sync.aligned.m16n8k8.row.col.f32.tf32.tf32.f32 "
                 "{%0,%1,%2,%3}, {%4,%5,%6,%7}, {%8,%9}, {%0,%1,%2,%3};"
                 : "+f"(d[0]), "+f"(d[1]), "+f"(d[2]), "+f"(d[3])
                 : "r"(a[0]), "r"(a[1]), "r"(a[2]), "r"(a[3]), "r"(b[0]), "r"(b[1]));
}

// per-matrix-group barrier (128 threads), id 1 or 2 within the CTA
__device__ __forceinline__ void gbar(int id) {
    asm volatile("bar.sync %0, 128;" :: "r"(id) : "memory");
}

// Warp computes a 32x32 tile of D = A * B (B read DIRECTLY as B[k][n], no symmetry
// assumption). NS=3 -> hi*hi + lo*hi + hi*lo (fp32-class, proven R4-equivalent);
// NS=1 -> plain tf32 (prep/scale only).
template<int NS>
__device__ __forceinline__ void warp_gemm(float acc[2][4][4],
                                          const float* __restrict__ As,
                                          const float* __restrict__ Bs,
                                          int mr, int nc, int g, int t4)
{
#pragma unroll
    for (int mt = 0; mt < 2; mt++)
#pragma unroll
        for (int nt = 0; nt < 4; nt++)
#pragma unroll
            for (int i = 0; i < 4; i++) acc[mt][nt][i] = 0.0f;

#pragma unroll
    for (int k0 = 0; k0 < 64; k0 += 8) {
        // B fragments first (shared by both m-tiles): b0=B[k0+t4][nc+8nt+g], b1=+4 rows
        unsigned bhi[4][2], blo[4][2];
        const float* bp0 = Bs + (k0 + t4) * LDSM + nc + g;
#pragma unroll
        for (int nt = 0; nt < 4; nt++) {
            float y0 = bp0[nt * 8];
            float y1 = bp0[4 * LDSM + nt * 8];
            bhi[nt][0] = f2tf(y0); bhi[nt][1] = f2tf(y1);
            if (NS == 3) {
                blo[nt][0] = f2tf(y0 - __uint_as_float(bhi[nt][0]));
                blo[nt][1] = f2tf(y1 - __uint_as_float(bhi[nt][1]));
            }
        }
#pragma unroll
        for (int mt = 0; mt < 2; mt++) {
            unsigned ahi[4], alo[4];
            const float* ap = As + (mr + mt * 16 + g) * LDSM + k0 + t4;
            float x0 = ap[0];
            float x1 = ap[8 * LDSM];
            float x2 = ap[4];
            float x3 = ap[8 * LDSM + 4];
            ahi[0] = f2tf(x0); ahi[1] = f2tf(x1); ahi[2] = f2tf(x2); ahi[3] = f2tf(x3);
            if (NS == 3) {
                alo[0] = f2tf(x0 - __uint_as_float(ahi[0]));
                alo[1] = f2tf(x1 - __uint_as_float(ahi[1]));
                alo[2] = f2tf(x2 - __uint_as_float(ahi[2]));
                alo[3] = f2tf(x3 - __uint_as_float(ahi[3]));
            }
#pragma unroll
            for (int nt = 0; nt < 4; nt++) {
                mma8(acc[mt][nt], ahi, bhi[nt]);
                if (NS == 3) {
                    mma8(acc[mt][nt], alo, bhi[nt]);
                    mma8(acc[mt][nt], ahi, blo[nt]);
                }
            }
        }
    }
}

__device__ __forceinline__ void store_acc(float* __restrict__ D, const float acc[2][4][4],
                                          int mr, int nc, int g, int t4)
{
#pragma unroll
    for (int mt = 0; mt < 2; mt++)
#pragma unroll
        for (int nt = 0; nt < 4; nt++) {
            int r = mr + mt * 16 + g, c = nc + nt * 8 + 2 * t4;
            *(float2*)&D[r * LDSM + c]       = make_float2(acc[mt][nt][0], acc[mt][nt][1]);
            *(float2*)&D[(r + 8) * LDSM + c] = make_float2(acc[mt][nt][2], acc[mt][nt][3]);
        }
}

#define GSZ (2 * 64 * LDSM + 16)   // floats per matrix group: S + P + red

extern "C" __global__ void __launch_bounds__(256, 3)
reeig5(const float* __restrict__ xg, float* __restrict__ outg, int nmat)
{
    extern __shared__ float sm[];
    const int gid = threadIdx.x >> 7;           // matrix slot within CTA
    const int t   = threadIdx.x & 127;
    const int mat = blockIdx.x * 2 + gid;
    if (mat >= nmat) return;                    // whole 128-thread group exits together

    const int warp = t >> 5, lane = t & 31;
    const int g = lane >> 2, t4 = lane & 3;
    const int mr = (warp & 1) * 32, nc = (warp >> 1) * 32;
    const int bid = 1 + gid;

    float* S   = sm + gid * GSZ;
    float* P   = S + 64 * LDSM;
    float* red = P + 64 * LDSM;

    const float* X = xg + (size_t)mat * 4096;
    float*       O = outg + (size_t)mat * 4096;

    // S <- A = X - eps*I
    for (int idx = t; idx < 4096; idx += 128) {
        int r = idx >> 6, c = idx & 63;
        float v = X[idx];
        if (r == c) v -= EPSV;
        S[r * LDSM + c] = v;
    }
    gbar(bid);

    float acc[2][4][4];

    // ---- scale estimate (single-TF32: feeds only s, 2% margin absorbs its error) ----
    warp_gemm<1>(acc, S, S, mr, nc, g, t4);     // P = A^2
    store_acc(P, acc, mr, nc, g, t4);
    gbar(bid);
    warp_gemm<1>(acc, P, P, mr, nc, g, t4);     // acc = A^4 (no store)
    float part = 0.0f;
#pragma unroll
    for (int mt = 0; mt < 2; mt++)
#pragma unroll
        for (int nt = 0; nt < 4; nt++)
#pragma unroll
            for (int i = 0; i < 4; i++) part = fmaf(acc[mt][nt][i], acc[mt][nt][i], part);
#pragma unroll
    for (int off = 16; off; off >>= 1)
        part += __shfl_xor_sync(0xffffffffu, part, off);
    if (lane == 0) red[warp] = part;
    gbar(bid);
    if (t == 0) {
        float tot = red[0] + red[1] + red[2] + red[3];
        // s = 1.02 * ||A^4||_F^(1/4) = 1.02 * tot^(1/8) >= 1.02 * lambda_max
        float s = 1.02f * exp2f(0.125f * log2f(fmaxf(tot, 1e-30f)));
        red[4] = 1.0f / s;
    }
    gbar(bid);
    const float inv_s = red[4];

    // S <- A / s  (spectrum in [-0.98, 0.98])
    for (int idx = t; idx < 4096; idx += 128)
        S[(idx >> 6) * LDSM + (idx & 63)] *= inv_s;
    gbar(bid);

    // ---- sign iterations: S <- ca*S + cb*S^3, in place ----
#pragma unroll 1
    for (int it = 0; it < NITER; it++) {
        const float ca = (it < NAGG) ? 2.325f      : 1.5f;
        const float cb = (it < NAGG) ? -1.8619375f : -0.5f;

        warp_gemm<3>(acc, S, S, mr, nc, g, t4);          // P = S^2
        store_acc(P, acc, mr, nc, g, t4);
        gbar(bid);

        warp_gemm<3>(acc, S, P, mr, nc, g, t4);          // acc = S^3
        // fold ca*S into acc (reads of S complete before barrier below)
#pragma unroll
        for (int mt = 0; mt < 2; mt++)
#pragma unroll
            for (int nt = 0; nt < 4; nt++) {
                int r = mr + mt * 16 + g, c = nc + nt * 8 + 2 * t4;
                float2 s1 = *(const float2*)&S[r * LDSM + c];
                float2 s2 = *(const float2*)&S[(r + 8) * LDSM + c];
                acc[mt][nt][0] = fmaf(cb, acc[mt][nt][0], ca * s1.x);
                acc[mt][nt][1] = fmaf(cb, acc[mt][nt][1], ca * s1.y);
                acc[mt][nt][2] = fmaf(cb, acc[mt][nt][2], ca * s2.x);
                acc[mt][nt][3] = fmaf(cb, acc[mt][nt][3], ca * s2.y);
            }
        gbar(bid);                                       // all S reads done
        store_acc(S, acc, mr, nc, g, t4);                // in-place update
        gbar(bid);
    }

    // ---- final: reload A, M = S*A ~= |A| ----
    for (int idx = t; idx < 4096; idx += 128) {
        int r = idx >> 6, c = idx & 63;
        float v = X[idx];
        if (r == c) v -= EPSV;
        P[r * LDSM + c] = v;                             // P <- A
    }
    gbar(bid);

    warp_gemm<3>(acc, S, P, mr, nc, g, t4);              // acc = M = S*A
    gbar(bid);                                           // all S reads done
    store_acc(S, acc, mr, nc, g, t4);                    // S <- M
    gbar(bid);

    // out = A/2 + eps*I + (M + M^T)/4
    for (int idx = t; idx < 4096; idx += 128) {
        int r = idx >> 6, c = idx & 63;
        float v = 0.5f * P[r * LDSM + c]
                + 0.25f * (S[r * LDSM + c] + S[c * LDSM + r]);
        if (r == c) v += EPSV;
        O[idx] = v;
    }
}

extern "C" void kernel_launch(void* const* d_in, const int* in_sizes, int n_in,
                              void* d_out, int out_size)
{
    const float* x  = (const float*)d_in[0];
    float* out      = (float*)d_out;
    const int nmat  = in_sizes[0] / 4096;

    const int smem_bytes = 2 * GSZ * (int)sizeof(float);   // 73856
    cudaFuncSetAttribute(reeig5, cudaFuncAttributeMaxDynamicSharedMemorySize,
                         smem_bytes);
    const int nblk = (nmat + 1) / 2;
    reeig5<<<nblk, 256, smem_bytes>>>(x, out, nmat);
}